// round 4
// baseline (speedup 1.0000x reference)
#include <cuda_runtime.h>
#include <math.h>

#define BB 128
#define SS 16
#define EE 512
#define RR 1000
#define G3 1536
#define NSCALE 0.04419417382415922f

// ---- device scratch (static, no allocations) ----
__device__ float GI_emb[RR * G3];
__device__ float H1_emb[RR * EE];
__device__ float GHH_emb[RR * G3];
__device__ float g_Krel[RR * EE];

__device__ float g_gi [BB * SS * G3];
__device__ float g_h1 [BB * SS * EE];
__device__ float g_ghh[BB * SS * G3];

__device__ int   g_src [BB * SS];
__device__ int   g_ord [BB * SS];
__device__ int   g_sel [BB];
__device__ int   g_dslot[BB];

__device__ float g_pair [BB * EE];
__device__ float g_q    [BB * EE];
__device__ float g_kpair[BB * EE];
__device__ float g_newx [BB * EE];
__device__ float g_newh1[BB * EE];
__device__ float g_scores[BB * (RR + 1)];
__device__ float g_prob  [BB * (RR + 1)];

typedef unsigned long long ull;
__device__ __forceinline__ ull pack2(float lo, float hi) {
    ull r; asm("mov.b64 %0, {%1, %2};" : "=l"(r) : "f"(lo), "f"(hi)); return r;
}
__device__ __forceinline__ void unpack2(ull v, float& lo, float& hi) {
    asm("mov.b64 {%0, %1}, %2;" : "=f"(lo), "=f"(hi) : "l"(v));
}
#define FMA2(acc, a, b) asm("fma.rn.f32x2 %0, %1, %2, %0;" : "+l"(acc) : "l"(a), "l"(b))

__device__ __forceinline__ float sigmf(float x) { return 1.0f / (1.0f + expf(-x)); }

__device__ __forceinline__ const float* p_gi(int b, int s) {
    int src = g_src[b * SS + s];
    return (src >= 0) ? &GI_emb[(size_t)src * G3] : &g_gi[((size_t)b * SS + s) * G3];
}
__device__ __forceinline__ const float* p_ghh(int b, int s) {
    int src = g_src[b * SS + s];
    return (src >= 0) ? &GHH_emb[(size_t)src * G3] : &g_ghh[((size_t)b * SS + s) * G3];
}
__device__ __forceinline__ const float* p_h1(int b, int s) {
    int src = g_src[b * SS + s];
    return (src >= 0) ? &H1_emb[(size_t)src * EE] : &g_h1[((size_t)b * SS + s) * EE];
}

__global__ void k_init(const int* __restrict__ tokens) {
    int b = blockIdx.x, t = threadIdx.x;
    if (t < SS) {
        g_ord[b * SS + t] = t;
        g_src[b * SS + t] = tokens[b * SS + t];
    }
}

// out[m][n] = dot(A[m,:512], W[n,:512]) * scale + bias[n]. 32x64 tile, 256 thr.
// flags&1: out row m -> out + (m*16 + g_dslot[m]) * ldout.
// If W2 != null, upper half of grid.x computes W2/bias2 -> out2.
__global__ __launch_bounds__(256) void gemm32(
    const float* __restrict__ A, const float* __restrict__ W,
    const float* __restrict__ bias, float* __restrict__ out,
    int M, int N, int ldout, int flags, float scale,
    const float* __restrict__ W2, const float* __restrict__ bias2,
    float* __restrict__ out2)
{
    __shared__ __align__(16) float As[16][34];
    __shared__ __align__(16) float Bs[16][66];
    const float* Wp = W; const float* bp = bias; float* op = out;
    int xt = blockIdx.x;
    if (W2) {
        int half = gridDim.x >> 1;
        if (xt >= half) { xt -= half; Wp = W2; bp = bias2; op = out2; }
    }
    int col0 = xt * 64, row0 = blockIdx.y * 32;
    int t = threadIdx.x;
    int tx = t & 15, ty = t >> 4;

    ull acc[2][2];
    ull zz = pack2(0.f, 0.f);
    acc[0][0] = zz; acc[0][1] = zz; acc[1][0] = zz; acc[1][1] = zz;

    for (int k0 = 0; k0 < 512; k0 += 16) {
#pragma unroll
        for (int i = 0; i < 2; i++) {
            int e = t + i * 256;
            int m = e >> 4, kk = e & 15;
            int gm = row0 + m;
            As[kk][m] = (gm < M) ? A[(size_t)gm * 512 + k0 + kk] : 0.f;
        }
#pragma unroll
        for (int i = 0; i < 4; i++) {
            int e = t + i * 256;
            int n = e >> 4, kk = e & 15;
            int gn = col0 + n;
            Bs[kk][n] = (gn < N) ? Wp[(size_t)gn * 512 + k0 + kk] : 0.f;
        }
        __syncthreads();
#pragma unroll
        for (int kk = 0; kk < 16; kk++) {
            ull b0 = *(const ull*)&Bs[kk][tx * 4];
            ull b1 = *(const ull*)&Bs[kk][tx * 4 + 2];
#pragma unroll
            for (int i = 0; i < 2; i++) {
                float a = As[kk][ty * 2 + i];
                ull a2 = pack2(a, a);
                FMA2(acc[i][0], a2, b0);
                FMA2(acc[i][1], a2, b1);
            }
        }
        __syncthreads();
    }
#pragma unroll
    for (int i = 0; i < 2; i++) {
        int gm = row0 + ty * 2 + i;
        if (gm >= M) continue;
        float* orow = (flags & 1) ? op + ((size_t)gm * SS + g_dslot[gm]) * (size_t)ldout
                                  : op + (size_t)gm * (size_t)ldout;
#pragma unroll
        for (int j = 0; j < 2; j++) {
            float lo, hi;
            unpack2(acc[i][j], lo, hi);
            int c = col0 + tx * 4 + j * 2;
            if (c < N)     orow[c]     = lo * scale + (bp ? bp[c]     : 0.f);
            if (c + 1 < N) orow[c + 1] = hi * scale + (bp ? bp[c + 1] : 0.f);
        }
    }
}

__global__ void k_h1emb(const float* __restrict__ b_hh) {
    int tk = blockIdx.x;
    const float* gi = &GI_emb[(size_t)tk * G3];
    for (int e = threadIdx.x; e < EE; e += blockDim.x) {
        float r = sigmf(gi[e] + b_hh[e]);
        float z = sigmf(gi[EE + e] + b_hh[EE + e]);
        float n = tanhf(gi[2 * EE + e] + r * b_hh[2 * EE + e]);
        H1_emb[(size_t)tk * EE + e] = (1.f - z) * n;
    }
}

__global__ void k_h1inc(const float* __restrict__ b_hh) {
    int b = blockIdx.x;
    int d = g_dslot[b];
    const float* gi = &g_gi[((size_t)b * SS + d) * G3];
    for (int e = threadIdx.x; e < EE; e += blockDim.x) {
        float r = sigmf(gi[e] + b_hh[e]);
        float z = sigmf(gi[EE + e] + b_hh[EE + e]);
        float n = tanhf(gi[2 * EE + e] + r * b_hh[2 * EE + e]);
        float h = (1.f - z) * n;
        g_h1[((size_t)b * SS + d) * EE + e] = h;
        g_newh1[(size_t)b * EE + e] = h;
    }
}

__device__ __forceinline__ float pair_elem(const float* gi, const float* gh,
                                           const float* h1, int e) {
    float r = sigmf(gi[e] + gh[e]);
    float z = sigmf(gi[EE + e] + gh[EE + e]);
    float n = tanhf(gi[2 * EE + e] + r * gh[2 * EE + e]);
    return (1.f - z) * n + z * h1[e];
}

__global__ void k_pairsel(const float* __restrict__ wfc, const float* __restrict__ bfc,
                          int npairs, int zloss, float* __restrict__ loss_out) {
    int b = blockIdx.x, t = threadIdx.x;
    __shared__ float red[256];
    __shared__ int sord[SS];
    __shared__ float sbest;
    __shared__ int sbestj;
    if (t < SS) sord[t] = g_ord[b * SS + t];
    if (t == 0) { sbest = -1e30f; sbestj = 0; }
    __syncthreads();

    if (npairs > 1) {
        for (int j = 0; j < npairs; j++) {
            const float* gi = p_gi(b, sord[j + 1]);
            const float* gh = p_ghh(b, sord[j]);
            const float* h1 = p_h1(b, sord[j]);
            float part = 0.f;
            for (int e = t; e < EE; e += 256)
                part += pair_elem(gi, gh, h1, e) * wfc[e];
            red[t] = part; __syncthreads();
            for (int s = 128; s > 0; s >>= 1) {
                if (t < s) red[t] += red[t + s];
                __syncthreads();
            }
            if (t == 0) {
                float sc = sigmf(red[0] + bfc[0]);
                if (sc > sbest) { sbest = sc; sbestj = j; }
            }
            __syncthreads();
        }
    }
    int j = sbestj;
    const float* gi = p_gi(b, sord[j + 1]);
    const float* gh = p_ghh(b, sord[j]);
    const float* h1 = p_h1(b, sord[j]);
    for (int e = t; e < EE; e += 256)
        g_pair[(size_t)b * EE + e] = pair_elem(gi, gh, h1, e);
    if (t == 0) {
        g_sel[b] = j;
        if (zloss >= 0) loss_out[b * SS + zloss] = 0.f;
    }
}

__device__ __forceinline__ float bsum(float v, float* red, int t) {
    red[t] = v; __syncthreads();
    for (int s = 128; s > 0; s >>= 1) { if (t < s) red[t] += red[t + s]; __syncthreads(); }
    return red[0];
}
__device__ __forceinline__ float bmax(float v, float* red, int t) {
    red[t] = v; __syncthreads();
    for (int s = 128; s > 0; s >>= 1) { if (t < s) red[t] = fmaxf(red[t], red[t + s]); __syncthreads(); }
    return red[0];
}

__global__ void k_softmax(int lossidx, int L, int do_book,
                          float* __restrict__ loss_out, float* __restrict__ scores_out) {
    int b = blockIdx.x, t = threadIdx.x;
    __shared__ float red[256];
    const float* q  = &g_q[(size_t)b * EE];
    const float* kp = &g_kpair[(size_t)b * EE];
    const float* sc = &g_scores[(size_t)b * (RR + 1)];

    float part = 0.f;
    for (int e = t; e < EE; e += 256) part += q[e] * kp[e];
    float c1000 = bsum(part, red, t) * NSCALE;
    __syncthreads();

    float m = -3.4e38f;
    for (int k = t; k <= RR; k += 256)
        m = fmaxf(m, (k < RR) ? sc[k] : c1000);
    m = bmax(m, red, t);
    __syncthreads();

    float se = 0.f, sv = 0.f;
    for (int k = t; k <= RR; k += 256) {
        float v = ((k < RR) ? sc[k] : c1000) - m;
        float ev = expf(v);
        se += ev; sv += ev * v;
    }
    float Z = bsum(se, red, t);
    __syncthreads();
    float S2 = bsum(sv, red, t);
    if (t == 0) loss_out[b * SS + lossidx] = logf(Z) - S2 / Z;

    float* pr = &g_prob[(size_t)b * (RR + 1)];
    for (int k = t; k <= RR; k += 256) {
        float raw = (k < RR) ? sc[k] : c1000;
        pr[k] = expf(raw - m) / Z;
        if (scores_out) scores_out[(size_t)b * (RR + 1) + k] = raw;
    }
    if (t == 0 && do_book) {
        int sel = g_sel[b];
        int* ord = &g_ord[b * SS];
        int slot = ord[sel];
        g_dslot[b] = slot;
        g_src[b * SS + slot] = -1;
        for (int i = sel + 1; i < L - 1; i++) ord[i] = ord[i + 1];
    }
}

__global__ __launch_bounds__(256) void k_merge(const float* __restrict__ emb) {
    int et = blockIdx.x, bt = blockIdx.y;
    int tx = threadIdx.x & 63, ty = threadIdx.x >> 6;
    int e = et * 64 + tx;
    __shared__ float sprob[16][128];
    float acc[4] = {0.f, 0.f, 0.f, 0.f};
    for (int r0 = 0; r0 < RR; r0 += 128) {
        for (int i = threadIdx.x; i < 16 * 128; i += 256) {
            int bb = i >> 7, rr = i & 127;
            int r = r0 + rr;
            sprob[bb][rr] = (r < RR) ? g_prob[(size_t)(bt * 16 + bb) * (RR + 1) + r] : 0.f;
        }
        __syncthreads();
        int rmax = min(128, RR - r0);
        for (int rr = 0; rr < rmax; rr++) {
            float ev = emb[(size_t)(r0 + rr) * EE + e];
#pragma unroll
            for (int i = 0; i < 4; i++)
                acc[i] += sprob[ty + i * 4][rr] * ev;
        }
        __syncthreads();
    }
#pragma unroll
    for (int i = 0; i < 4; i++) {
        int b = bt * 16 + ty + i * 4;
        float mg = acc[i] + g_prob[(size_t)b * (RR + 1) + RR] * g_pair[(size_t)b * EE + e];
        g_newx[(size_t)b * EE + e] = mg;
    }
}

// ---------------- host ----------------
extern "C" void kernel_launch(void* const* d_in, const int* in_sizes, int n_in,
                              void* d_out, int out_size) {
    const int*   tokens = (const int*)  d_in[0];
    const float* emb    = (const float*)d_in[1];
    const float* W_ih   = (const float*)d_in[2];
    const float* W_hh   = (const float*)d_in[3];
    const float* b_ih   = (const float*)d_in[4];
    const float* b_hh   = (const float*)d_in[5];
    const float* w_fc   = (const float*)d_in[6];
    const float* b_fc   = (const float*)d_in[7];
    const float* Wq     = (const float*)d_in[8];
    const float* bq     = (const float*)d_in[9];
    const float* Wk     = (const float*)d_in[10];
    const float* bk     = (const float*)d_in[11];

    float* out_scores = (float*)d_out;                       // 128 x 1001
    float* out_loss   = (float*)d_out + (size_t)BB * (RR + 1); // 128 x 16

    float *GI, *H1, *GHH, *Krel, *gi, *ghh, *pair, *q, *kpair, *newx, *newh1, *scores;
    cudaGetSymbolAddress((void**)&GI, GI_emb);
    cudaGetSymbolAddress((void**)&H1, H1_emb);
    cudaGetSymbolAddress((void**)&GHH, GHH_emb);
    cudaGetSymbolAddress((void**)&Krel, g_Krel);
    cudaGetSymbolAddress((void**)&gi, g_gi);
    cudaGetSymbolAddress((void**)&ghh, g_ghh);
    cudaGetSymbolAddress((void**)&pair, g_pair);
    cudaGetSymbolAddress((void**)&q, g_q);
    cudaGetSymbolAddress((void**)&kpair, g_kpair);
    cudaGetSymbolAddress((void**)&newx, g_newx);
    cudaGetSymbolAddress((void**)&newh1, g_newh1);
    cudaGetSymbolAddress((void**)&scores, g_scores);

    k_init<<<BB, 32>>>(tokens);
    gemm32<<<dim3(24, 32), 256>>>(emb, W_ih, b_ih, GI, RR, G3, G3, 0, 1.f, NULL, NULL, NULL);
    k_h1emb<<<RR, 256>>>(b_hh);
    gemm32<<<dim3(24, 32), 256>>>(H1, W_hh, b_hh, GHH, RR, G3, G3, 0, 1.f, NULL, NULL, NULL);
    gemm32<<<dim3(8, 32), 256>>>(emb, Wk, bk, Krel, RR, EE, EE, 0, 1.f, NULL, NULL, NULL);

    for (int i = 0; i < 14; i++) {
        int L = SS - i;
        k_pairsel<<<BB, 256>>>(w_fc, b_fc, L - 1, -1, out_loss);
        gemm32<<<dim3(16, 4), 256>>>(pair, Wq, bq, q, BB, EE, EE, 0, 1.f, Wk, bk, kpair);
        gemm32<<<dim3(16, 4), 256>>>(q, Krel, NULL, scores, BB, RR, RR + 1, 0, NSCALE,
                                     NULL, NULL, NULL);
        k_softmax<<<BB, 256>>>(i, L, 1, out_loss, NULL);
        k_merge<<<dim3(8, 8), 256>>>(emb);
        gemm32<<<dim3(24, 4), 256>>>(newx, W_ih, b_ih, gi, BB, G3, G3, 1, 1.f, NULL, NULL, NULL);
        k_h1inc<<<BB, 256>>>(b_hh);
        gemm32<<<dim3(24, 4), 256>>>(newh1, W_hh, b_hh, ghh, BB, G3, G3, 1, 1.f, NULL, NULL, NULL);
    }
    // Round 15: L=2 -> x' = gru(x1, gru(x0, 0)) = pairs[0]; loss[14] = 0
    k_pairsel<<<BB, 256>>>(w_fc, b_fc, 1, 14, out_loss);
    // Final attention on the single remaining vector
    gemm32<<<dim3(16, 4), 256>>>(pair, Wq, bq, q, BB, EE, EE, 0, 1.f, Wk, bk, kpair);
    gemm32<<<dim3(16, 4), 256>>>(q, Krel, NULL, scores, BB, RR, RR + 1, 0, NSCALE,
                                 NULL, NULL, NULL);
    k_softmax<<<BB, 256>>>(15, 0, 0, out_loss, out_scores);
}

// round 5
// speedup vs baseline: 1.0861x; 1.0861x over previous
#include <cuda_runtime.h>
#include <math.h>

#define BB 128
#define SS 16
#define EE 512
#define RR 1000
#define G3 1536
#define NSCALE 0.04419417382415922f

// ---- device scratch (static, no allocations) ----
__device__ float GI_emb[RR * G3];
__device__ float H1_emb[RR * EE];
__device__ float GHH_emb[RR * G3];
__device__ float g_Krel[RR * EE];

__device__ float g_gi [BB * SS * G3];
__device__ float g_h1 [BB * SS * EE];
__device__ float g_ghh[BB * SS * G3];

__device__ int   g_src [BB * SS];
__device__ int   g_ord [BB * SS];
__device__ int   g_sel [BB];
__device__ int   g_dslot[BB];
__device__ float g_pscore[BB * SS];

__device__ float g_pair [BB * EE];
__device__ float g_q    [BB * EE];
__device__ float g_kpair[BB * EE];
__device__ float g_newx [BB * EE];
__device__ float g_newh1[BB * EE];
__device__ float g_scores[BB * (RR + 1)];
__device__ float g_prob  [BB * (RR + 1)];

typedef unsigned long long ull;
__device__ __forceinline__ ull pack2(float lo, float hi) {
    ull r; asm("mov.b64 %0, {%1, %2};" : "=l"(r) : "f"(lo), "f"(hi)); return r;
}
__device__ __forceinline__ void unpack2(ull v, float& lo, float& hi) {
    asm("mov.b64 {%0, %1}, %2;" : "=f"(lo), "=f"(hi) : "l"(v));
}
#define FMA2(acc, a, b) asm("fma.rn.f32x2 %0, %1, %2, %0;" : "+l"(acc) : "l"(a), "l"(b))

__device__ __forceinline__ float sigmf(float x) { return 1.0f / (1.0f + expf(-x)); }

__device__ __forceinline__ const float* p_gi(int b, int s) {
    int src = g_src[b * SS + s];
    return (src >= 0) ? &GI_emb[(size_t)src * G3] : &g_gi[((size_t)b * SS + s) * G3];
}
__device__ __forceinline__ const float* p_ghh(int b, int s) {
    int src = g_src[b * SS + s];
    return (src >= 0) ? &GHH_emb[(size_t)src * G3] : &g_ghh[((size_t)b * SS + s) * G3];
}
__device__ __forceinline__ const float* p_h1(int b, int s) {
    int src = g_src[b * SS + s];
    return (src >= 0) ? &H1_emb[(size_t)src * EE] : &g_h1[((size_t)b * SS + s) * EE];
}

__global__ void k_init(const int* __restrict__ tokens) {
    int b = blockIdx.x, t = threadIdx.x;
    if (t < SS) {
        g_ord[b * SS + t] = t;
        g_src[b * SS + t] = tokens[b * SS + t];
    }
}

// out[m][n] = dot(A[m,:512], W[n,:512]) * scale + bias[n].
// TM x 64 tile, 256 threads, 4x4 (or 2x4) register blocking with f32x2 FMA.
// flags&1: out row m -> out + (m*16 + g_dslot[m]) * ldout.
// If W2 != null, upper half of grid.x computes W2/bias2 -> out2.
template<int TM>
__global__ __launch_bounds__(256) void gemm_t(
    const float* __restrict__ A, const float* __restrict__ W,
    const float* __restrict__ bias, float* __restrict__ out,
    int M, int N, int ldout, int flags, float scale,
    const float* __restrict__ W2, const float* __restrict__ bias2,
    float* __restrict__ out2)
{
    __shared__ __align__(16) float As[16][TM + 4];
    __shared__ __align__(16) float Bs[16][68];
    const float* Wp = W; const float* bp = bias; float* op = out;
    int xt = blockIdx.x;
    if (W2) {
        int half = gridDim.x >> 1;
        if (xt >= half) { xt -= half; Wp = W2; bp = bias2; op = out2; }
    }
    int col0 = xt * 64, row0 = blockIdx.y * TM;
    int t = threadIdx.x;
    int tx = t & 15, ty = t >> 4;
    constexpr int RPT = TM / 16;  // 4 (TM=64) or 2 (TM=32)

    ull acc[RPT][2];
#pragma unroll
    for (int i = 0; i < RPT; i++) { acc[i][0] = 0ULL; acc[i][1] = 0ULL; }

    for (int k0 = 0; k0 < 512; k0 += 16) {
        // load A tile: TM rows x 16 k, float4 per slot
#pragma unroll
        for (int s = t; s < TM * 4; s += 256) {
            int m = s >> 2, kg = s & 3;
            int gm = row0 + m;
            float4 av = make_float4(0.f, 0.f, 0.f, 0.f);
            if (gm < M) av = *(const float4*)&A[(size_t)gm * 512 + k0 + kg * 4];
            As[kg * 4 + 0][m] = av.x; As[kg * 4 + 1][m] = av.y;
            As[kg * 4 + 2][m] = av.z; As[kg * 4 + 3][m] = av.w;
        }
        // load B tile: 64 rows x 16 k
        {
            int n = t >> 2, kg = t & 3;
            int gn = col0 + n;
            float4 bv = make_float4(0.f, 0.f, 0.f, 0.f);
            if (gn < N) bv = *(const float4*)&Wp[(size_t)gn * 512 + k0 + kg * 4];
            Bs[kg * 4 + 0][n] = bv.x; Bs[kg * 4 + 1][n] = bv.y;
            Bs[kg * 4 + 2][n] = bv.z; Bs[kg * 4 + 3][n] = bv.w;
        }
        __syncthreads();
#pragma unroll
        for (int kk = 0; kk < 16; kk++) {
            ull b0 = *(const ull*)&Bs[kk][tx * 4];
            ull b1 = *(const ull*)&Bs[kk][tx * 4 + 2];
            if constexpr (TM == 64) {
                float4 a = *(const float4*)&As[kk][ty * 4];
                ull a0 = pack2(a.x, a.x), a1 = pack2(a.y, a.y);
                ull a2 = pack2(a.z, a.z), a3 = pack2(a.w, a.w);
                FMA2(acc[0][0], a0, b0); FMA2(acc[0][1], a0, b1);
                FMA2(acc[1][0], a1, b0); FMA2(acc[1][1], a1, b1);
                FMA2(acc[2][0], a2, b0); FMA2(acc[2][1], a2, b1);
                FMA2(acc[3][0], a3, b0); FMA2(acc[3][1], a3, b1);
            } else {
                float2 a = *(const float2*)&As[kk][ty * 2];
                ull a0 = pack2(a.x, a.x), a1 = pack2(a.y, a.y);
                FMA2(acc[0][0], a0, b0); FMA2(acc[0][1], a0, b1);
                FMA2(acc[1][0], a1, b0); FMA2(acc[1][1], a1, b1);
            }
        }
        __syncthreads();
    }
#pragma unroll
    for (int i = 0; i < RPT; i++) {
        int gm = row0 + ty * RPT + i;
        if (gm >= M) continue;
        float* orow = (flags & 1) ? op + ((size_t)gm * SS + g_dslot[gm]) * (size_t)ldout
                                  : op + (size_t)gm * (size_t)ldout;
#pragma unroll
        for (int j = 0; j < 2; j++) {
            float lo, hi;
            unpack2(acc[i][j], lo, hi);
            int c = col0 + tx * 4 + j * 2;
            if (c < N)     orow[c]     = lo * scale + (bp ? bp[c]     : 0.f);
            if (c + 1 < N) orow[c + 1] = hi * scale + (bp ? bp[c + 1] : 0.f);
        }
    }
}

__global__ void k_h1emb(const float* __restrict__ b_hh) {
    int tk = blockIdx.x;
    const float* gi = &GI_emb[(size_t)tk * G3];
    for (int e = threadIdx.x; e < EE; e += blockDim.x) {
        float r = sigmf(gi[e] + b_hh[e]);
        float z = sigmf(gi[EE + e] + b_hh[EE + e]);
        float n = tanhf(gi[2 * EE + e] + r * b_hh[2 * EE + e]);
        H1_emb[(size_t)tk * EE + e] = (1.f - z) * n;
    }
}

__global__ void k_h1inc(const float* __restrict__ b_hh) {
    int b = blockIdx.x;
    int d = g_dslot[b];
    const float* gi = &g_gi[((size_t)b * SS + d) * G3];
    for (int e = threadIdx.x; e < EE; e += blockDim.x) {
        float r = sigmf(gi[e] + b_hh[e]);
        float z = sigmf(gi[EE + e] + b_hh[EE + e]);
        float n = tanhf(gi[2 * EE + e] + r * b_hh[2 * EE + e]);
        float h = (1.f - z) * n;
        g_h1[((size_t)b * SS + d) * EE + e] = h;
        g_newh1[(size_t)b * EE + e] = h;
    }
}

__device__ __forceinline__ float pair_elem(const float* gi, const float* gh,
                                           const float* h1, int e) {
    float r = sigmf(gi[e] + gh[e]);
    float z = sigmf(gi[EE + e] + gh[EE + e]);
    float n = tanhf(gi[2 * EE + e] + r * gh[2 * EE + e]);
    return (1.f - z) * n + z * h1[e];
}

// Incremental pair scoring: only pairs (prev_sel-1, prev_sel) changed since the
// last round; all other scores come from g_pscore (shifted in bookkeeping).
__global__ void k_pairsel(const float* __restrict__ wfc, const float* __restrict__ bfc,
                          int npairs, int zloss, float* __restrict__ loss_out, int first) {
    int b = blockIdx.x, t = threadIdx.x;
    int w = t >> 5, lane = t & 31;
    __shared__ int sord[SS];
    __shared__ float sps[SS];
    __shared__ int sbestj;
    if (t < SS) {
        sord[t] = g_ord[b * SS + t];
        sps[t]  = g_pscore[b * SS + t];
    }
    int prev_sel = g_sel[b];
    __syncthreads();

    int j0 = -1, j1 = -1;  // per-warp recompute assignments
    if (first) {
        j0 = w;
        j1 = w + 8;
        if (j0 >= npairs) j0 = -1;
        if (j1 >= npairs) j1 = -1;
    } else {
        int cnt = 0, jj[2];
        if (prev_sel - 1 >= 0 && prev_sel - 1 < npairs) jj[cnt++] = prev_sel - 1;
        if (prev_sel >= 0 && prev_sel < npairs)         jj[cnt++] = prev_sel;
        if (w < cnt) j0 = jj[w];
    }
#pragma unroll
    for (int rep = 0; rep < 2; rep++) {
        int j = (rep == 0) ? j0 : j1;
        if (j >= 0) {
            const float* gi = p_gi(b, sord[j + 1]);
            const float* gh = p_ghh(b, sord[j]);
            const float* h1 = p_h1(b, sord[j]);
            float s = 0.f;
            for (int e = lane; e < EE; e += 32)
                s += pair_elem(gi, gh, h1, e) * wfc[e];
#pragma unroll
            for (int off = 16; off > 0; off >>= 1)
                s += __shfl_down_sync(0xffffffffu, s, off);
            if (lane == 0) {
                float sc = sigmf(s + bfc[0]);
                sps[j] = sc;
                g_pscore[b * SS + j] = sc;
            }
        }
    }
    __syncthreads();

    if (t == 0) {
        int bj = 0; float bs = sps[0];
        for (int j = 1; j < npairs; j++)
            if (sps[j] > bs) { bs = sps[j]; bj = j; }
        sbestj = bj;
        g_sel[b] = bj;
        if (zloss >= 0) loss_out[b * SS + zloss] = 0.f;
    }
    __syncthreads();
    int j = sbestj;
    const float* gi = p_gi(b, sord[j + 1]);
    const float* gh = p_ghh(b, sord[j]);
    const float* h1 = p_h1(b, sord[j]);
    for (int e = t; e < EE; e += 256)
        g_pair[(size_t)b * EE + e] = pair_elem(gi, gh, h1, e);
}

__device__ __forceinline__ float bsum(float v, float* red, int t) {
    red[t] = v; __syncthreads();
    for (int s = 128; s > 0; s >>= 1) { if (t < s) red[t] += red[t + s]; __syncthreads(); }
    return red[0];
}
__device__ __forceinline__ float bmax(float v, float* red, int t) {
    red[t] = v; __syncthreads();
    for (int s = 128; s > 0; s >>= 1) { if (t < s) red[t] = fmaxf(red[t], red[t + s]); __syncthreads(); }
    return red[0];
}

__global__ void k_softmax(int lossidx, int L, int do_book,
                          float* __restrict__ loss_out, float* __restrict__ scores_out) {
    int b = blockIdx.x, t = threadIdx.x;
    __shared__ float red[256];
    const float* q  = &g_q[(size_t)b * EE];
    const float* kp = &g_kpair[(size_t)b * EE];
    const float* sc = &g_scores[(size_t)b * (RR + 1)];

    float part = 0.f;
    for (int e = t; e < EE; e += 256) part += q[e] * kp[e];
    float c1000 = bsum(part, red, t) * NSCALE;
    __syncthreads();

    float m = -3.4e38f;
    for (int k = t; k <= RR; k += 256)
        m = fmaxf(m, (k < RR) ? sc[k] : c1000);
    m = bmax(m, red, t);
    __syncthreads();

    float se = 0.f, sv = 0.f;
    for (int k = t; k <= RR; k += 256) {
        float v = ((k < RR) ? sc[k] : c1000) - m;
        float ev = expf(v);
        se += ev; sv += ev * v;
    }
    float Z = bsum(se, red, t);
    __syncthreads();
    float S2 = bsum(sv, red, t);
    if (t == 0) loss_out[b * SS + lossidx] = logf(Z) - S2 / Z;

    float* pr = &g_prob[(size_t)b * (RR + 1)];
    for (int k = t; k <= RR; k += 256) {
        float raw = (k < RR) ? sc[k] : c1000;
        pr[k] = expf(raw - m) / Z;
        if (scores_out) scores_out[(size_t)b * (RR + 1) + k] = raw;
    }
    if (t == 0 && do_book) {
        int sel = g_sel[b];
        int* ord = &g_ord[b * SS];
        float* ps = &g_pscore[b * SS];
        int slot = ord[sel];
        g_dslot[b] = slot;
        g_src[b * SS + slot] = -1;
        for (int i = sel + 1; i < L - 1; i++) { ord[i] = ord[i + 1]; ps[i] = ps[i + 1]; }
    }
}

// merged[b][e] = sum_r prob[b][r] * emb[r][e] + prob[b][1000] * pair[b][e]
// GEMM-style: M=128 (b), N=512 (e), K=1000 (r). 32x64 tile, f32x2.
__global__ __launch_bounds__(256) void k_merge(const float* __restrict__ emb) {
    __shared__ __align__(16) float As[16][36];
    __shared__ __align__(16) float Bs[16][68];
    int col0 = blockIdx.x * 64, row0 = blockIdx.y * 32;
    int t = threadIdx.x, tx = t & 15, ty = t >> 4;

    ull acc[2][2] = {{0ULL, 0ULL}, {0ULL, 0ULL}};

    for (int k0 = 0; k0 < RR; k0 += 16) {
        if (t < 128) {
            int m = t >> 2, kg = t & 3;
            const float* pr = &g_prob[(size_t)(row0 + m) * (RR + 1) + k0 + kg * 4];
#pragma unroll
            for (int u = 0; u < 4; u++) {
                int k = k0 + kg * 4 + u;
                As[kg * 4 + u][m] = (k < RR) ? pr[u] : 0.f;
            }
        }
        {
            int rr = t >> 4, eg = t & 15;
            int r = k0 + rr;
            float4 bv = make_float4(0.f, 0.f, 0.f, 0.f);
            if (r < RR) bv = *(const float4*)&emb[(size_t)r * EE + col0 + eg * 4];
            Bs[rr][eg * 4 + 0] = bv.x; Bs[rr][eg * 4 + 1] = bv.y;
            Bs[rr][eg * 4 + 2] = bv.z; Bs[rr][eg * 4 + 3] = bv.w;
        }
        __syncthreads();
#pragma unroll
        for (int kk = 0; kk < 16; kk++) {
            ull b0 = *(const ull*)&Bs[kk][tx * 4];
            ull b1 = *(const ull*)&Bs[kk][tx * 4 + 2];
            float2 a = *(const float2*)&As[kk][ty * 2];
            ull a0 = pack2(a.x, a.x), a1 = pack2(a.y, a.y);
            FMA2(acc[0][0], a0, b0); FMA2(acc[0][1], a0, b1);
            FMA2(acc[1][0], a1, b0); FMA2(acc[1][1], a1, b1);
        }
        __syncthreads();
    }
#pragma unroll
    for (int i = 0; i < 2; i++) {
        int b = row0 + ty * 2 + i;
        float pw = g_prob[(size_t)b * (RR + 1) + RR];
#pragma unroll
        for (int j = 0; j < 2; j++) {
            float lo, hi;
            unpack2(acc[i][j], lo, hi);
            int c = col0 + tx * 4 + j * 2;
            g_newx[(size_t)b * EE + c]     = lo + pw * g_pair[(size_t)b * EE + c];
            g_newx[(size_t)b * EE + c + 1] = hi + pw * g_pair[(size_t)b * EE + c + 1];
        }
    }
}

// ---------------- host ----------------
extern "C" void kernel_launch(void* const* d_in, const int* in_sizes, int n_in,
                              void* d_out, int out_size) {
    const int*   tokens = (const int*)  d_in[0];
    const float* emb    = (const float*)d_in[1];
    const float* W_ih   = (const float*)d_in[2];
    const float* W_hh   = (const float*)d_in[3];
    const float* b_ih   = (const float*)d_in[4];
    const float* b_hh   = (const float*)d_in[5];
    const float* w_fc   = (const float*)d_in[6];
    const float* b_fc   = (const float*)d_in[7];
    const float* Wq     = (const float*)d_in[8];
    const float* bq     = (const float*)d_in[9];
    const float* Wk     = (const float*)d_in[10];
    const float* bk     = (const float*)d_in[11];

    float* out_scores = (float*)d_out;                         // 128 x 1001
    float* out_loss   = (float*)d_out + (size_t)BB * (RR + 1); // 128 x 16

    float *GI, *H1, *GHH, *Krel, *gi, *ghh, *pair, *q, *kpair, *newx, *newh1, *scores;
    cudaGetSymbolAddress((void**)&GI, GI_emb);
    cudaGetSymbolAddress((void**)&H1, H1_emb);
    cudaGetSymbolAddress((void**)&GHH, GHH_emb);
    cudaGetSymbolAddress((void**)&Krel, g_Krel);
    cudaGetSymbolAddress((void**)&gi, g_gi);
    cudaGetSymbolAddress((void**)&ghh, g_ghh);
    cudaGetSymbolAddress((void**)&pair, g_pair);
    cudaGetSymbolAddress((void**)&q, g_q);
    cudaGetSymbolAddress((void**)&kpair, g_kpair);
    cudaGetSymbolAddress((void**)&newx, g_newx);
    cudaGetSymbolAddress((void**)&newh1, g_newh1);
    cudaGetSymbolAddress((void**)&scores, g_scores);

    k_init<<<BB, 32>>>(tokens);
    gemm_t<64><<<dim3(24, 16), 256>>>(emb, W_ih, b_ih, GI, RR, G3, G3, 0, 1.f, NULL, NULL, NULL);
    k_h1emb<<<RR, 256>>>(b_hh);
    gemm_t<64><<<dim3(24, 16), 256>>>(H1, W_hh, b_hh, GHH, RR, G3, G3, 0, 1.f, NULL, NULL, NULL);
    gemm_t<64><<<dim3(8, 16), 256>>>(emb, Wk, bk, Krel, RR, EE, EE, 0, 1.f, NULL, NULL, NULL);

    for (int i = 0; i < 14; i++) {
        int L = SS - i;
        k_pairsel<<<BB, 256>>>(w_fc, b_fc, L - 1, -1, out_loss, i == 0);
        gemm_t<32><<<dim3(16, 4), 256>>>(pair, Wq, bq, q, BB, EE, EE, 0, 1.f, Wk, bk, kpair);
        gemm_t<32><<<dim3(16, 4), 256>>>(q, Krel, NULL, scores, BB, RR, RR + 1, 0, NSCALE,
                                         NULL, NULL, NULL);
        k_softmax<<<BB, 256>>>(i, L, 1, out_loss, NULL);
        k_merge<<<dim3(8, 4), 256>>>(emb);
        gemm_t<32><<<dim3(24, 4), 256>>>(newx, W_ih, b_ih, gi, BB, G3, G3, 1, 1.f, NULL, NULL, NULL);
        k_h1inc<<<BB, 256>>>(b_hh);
        gemm_t<32><<<dim3(24, 4), 256>>>(newh1, W_hh, b_hh, ghh, BB, G3, G3, 1, 1.f, NULL, NULL, NULL);
    }
    // Round 15: L=2 -> merged = gru(x1, gru(x0, 0)) = pairs[0]; loss[14] = 0
    k_pairsel<<<BB, 256>>>(w_fc, b_fc, 1, 14, out_loss, 0);
    gemm_t<32><<<dim3(16, 4), 256>>>(pair, Wq, bq, q, BB, EE, EE, 0, 1.f, Wk, bk, kpair);
    gemm_t<32><<<dim3(16, 4), 256>>>(q, Krel, NULL, scores, BB, RR, RR + 1, 0, NSCALE,
                                     NULL, NULL, NULL);
    k_softmax<<<BB, 256>>>(15, 0, 0, out_loss, out_scores);
}

// round 6
// speedup vs baseline: 1.7083x; 1.5730x over previous
#include <cuda_runtime.h>
#include <math.h>

#define BB 128
#define SS 16
#define EE 512
#define RR 1000
#define G3 1536
#define NSCALE 0.04419417382415922f

// ---- device scratch (static, no allocations) ----
__device__ float GI_emb[RR * G3];
__device__ float H1_emb[RR * EE];
__device__ float GHH_emb[RR * G3];
__device__ float g_Krel[RR * EE];
__device__ float g_KW[RR * EE];
__device__ float g_cs[RR];

__device__ float g_gi [BB * SS * G3];
__device__ float g_h1 [BB * SS * EE];
__device__ float g_ghh[BB * SS * G3];

__device__ int   g_src [BB * SS];
__device__ int   g_ord [BB * SS];
__device__ int   g_sel [BB];
__device__ int   g_dslot[BB];
__device__ float g_pscore[BB * SS];

__device__ float g_pair [BB * EE];
__device__ float g_q    [BB * EE];
__device__ float g_kpair[BB * EE];
__device__ float g_giP  [BB * G3];
__device__ float g_newh1[BB * EE];
__device__ float g_scores[BB * (RR + 1)];
__device__ float g_prob  [BB * (RR + 1) + 16];

typedef unsigned long long ull;
__device__ __forceinline__ ull pack2(float lo, float hi) {
    ull r; asm("mov.b64 %0, {%1, %2};" : "=l"(r) : "f"(lo), "f"(hi)); return r;
}
__device__ __forceinline__ void unpack2(ull v, float& lo, float& hi) {
    asm("mov.b64 {%0, %1}, %2;" : "=f"(lo), "=f"(hi) : "l"(v));
}
#define FMA2(acc, a, b) asm("fma.rn.f32x2 %0, %1, %2, %0;" : "+l"(acc) : "l"(a), "l"(b))

__device__ __forceinline__ float sigmf(float x) { return 1.0f / (1.0f + expf(-x)); }

__device__ __forceinline__ const float* p_gi(int b, int s) {
    int src = g_src[b * SS + s];
    return (src >= 0) ? &GI_emb[(size_t)src * G3] : &g_gi[((size_t)b * SS + s) * G3];
}
__device__ __forceinline__ const float* p_ghh(int b, int s) {
    int src = g_src[b * SS + s];
    return (src >= 0) ? &GHH_emb[(size_t)src * G3] : &g_ghh[((size_t)b * SS + s) * G3];
}
__device__ __forceinline__ const float* p_h1(int b, int s) {
    int src = g_src[b * SS + s];
    return (src >= 0) ? &H1_emb[(size_t)src * EE] : &g_h1[((size_t)b * SS + s) * EE];
}

__global__ void k_init(const int* __restrict__ tokens) {
    int b = blockIdx.x, t = threadIdx.x;
    if (t < SS) {
        g_ord[b * SS + t] = t;
        g_src[b * SS + t] = tokens[b * SS + t];
    }
}

// ================= GEMM: out[m][n] = dot(A[m,:512], W[n,:512])*scale + bias[n]
// B is N-row-major (W[n][k]). Double-buffered GMEM->reg prefetch.
// flags&1: row m stored at out + (m*16 + g_dslot[m]) * ldout.
template<int TM>
__global__ __launch_bounds__(256) void gemm_t(
    const float* __restrict__ A, const float* __restrict__ W,
    const float* __restrict__ bias, float* __restrict__ out,
    int M, int N, int ldout, int flags, float scale)
{
    __shared__ __align__(16) float As[16][TM + 4];
    __shared__ __align__(16) float Bs[16][68];
    int col0 = blockIdx.x * 64, row0 = blockIdx.y * TM;
    int t = threadIdx.x, tx = t & 15, ty = t >> 4;
    constexpr int RPT = TM / 16;
    ull acc[RPT][2];
#pragma unroll
    for (int i = 0; i < RPT; i++) { acc[i][0] = 0ULL; acc[i][1] = 0ULL; }

    int am = t >> 2, akg = t & 3;
    bool hasA = (TM == 64) || (t < 128);
    int gmA = row0 + am;
    int bn = t >> 2, bkg = t & 3;
    int gnB = col0 + bn;

    float4 ra = make_float4(0.f,0.f,0.f,0.f), rb = make_float4(0.f,0.f,0.f,0.f);
    if (hasA && gmA < M) ra = *(const float4*)&A[(size_t)gmA * 512 + akg * 4];
    if (gnB < N)         rb = *(const float4*)&W[(size_t)gnB * 512 + bkg * 4];

    for (int it = 0; it < 32; it++) {
        if (hasA) {
            As[akg*4+0][am] = ra.x; As[akg*4+1][am] = ra.y;
            As[akg*4+2][am] = ra.z; As[akg*4+3][am] = ra.w;
        }
        Bs[bkg*4+0][bn] = rb.x; Bs[bkg*4+1][bn] = rb.y;
        Bs[bkg*4+2][bn] = rb.z; Bs[bkg*4+3][bn] = rb.w;
        __syncthreads();
        if (it < 31) {
            int k0 = (it + 1) * 16;
            ra = (hasA && gmA < M) ? *(const float4*)&A[(size_t)gmA*512 + k0 + akg*4]
                                   : make_float4(0.f,0.f,0.f,0.f);
            rb = (gnB < N) ? *(const float4*)&W[(size_t)gnB*512 + k0 + bkg*4]
                           : make_float4(0.f,0.f,0.f,0.f);
        }
#pragma unroll
        for (int kk = 0; kk < 16; kk++) {
            ull b0 = *(const ull*)&Bs[kk][tx*4];
            ull b1 = *(const ull*)&Bs[kk][tx*4+2];
            if constexpr (TM == 64) {
                float4 a = *(const float4*)&As[kk][ty*4];
                ull a0=pack2(a.x,a.x), a1=pack2(a.y,a.y);
                ull a2=pack2(a.z,a.z), a3=pack2(a.w,a.w);
                FMA2(acc[0][0],a0,b0); FMA2(acc[0][1],a0,b1);
                FMA2(acc[1][0],a1,b0); FMA2(acc[1][1],a1,b1);
                FMA2(acc[2][0],a2,b0); FMA2(acc[2][1],a2,b1);
                FMA2(acc[3][0],a3,b0); FMA2(acc[3][1],a3,b1);
            } else {
                float2 a = *(const float2*)&As[kk][ty*2];
                ull a0=pack2(a.x,a.x), a1=pack2(a.y,a.y);
                FMA2(acc[0][0],a0,b0); FMA2(acc[0][1],a0,b1);
                FMA2(acc[1][0],a1,b0); FMA2(acc[1][1],a1,b1);
            }
        }
        __syncthreads();
    }
#pragma unroll
    for (int i = 0; i < RPT; i++) {
        int gm = row0 + ty * RPT + i;
        if (gm >= M) continue;
        float* orow = (flags & 1) ? out + ((size_t)gm * SS + g_dslot[gm]) * (size_t)ldout
                                  : out + (size_t)gm * (size_t)ldout;
#pragma unroll
        for (int j = 0; j < 2; j++) {
            float lo, hi;
            unpack2(acc[i][j], lo, hi);
            int c = col0 + tx * 4 + j * 2;
            if (c < N)     orow[c]     = lo * scale + (bias ? bias[c]     : 0.f);
            if (c + 1 < N) orow[c + 1] = hi * scale + (bias ? bias[c + 1] : 0.f);
        }
    }
}

// ================= GEMM with B K-row-major: out[m][n] = sum_k A[m][k]*B[k][n]
// Used for KW = Krel @ Wq. TM=64, K=512, double-buffered.
__global__ __launch_bounds__(256) void k_gemm_kn(
    const float* __restrict__ A, const float* __restrict__ B,
    float* __restrict__ out, int M, int N, int ldb)
{
    __shared__ __align__(16) float As[16][68];
    __shared__ __align__(16) float Bs[16][68];
    int col0 = blockIdx.x * 64, row0 = blockIdx.y * 64;
    int t = threadIdx.x, tx = t & 15, ty = t >> 4;
    ull acc[4][2];
#pragma unroll
    for (int i = 0; i < 4; i++) { acc[i][0] = 0ULL; acc[i][1] = 0ULL; }

    int am = t >> 2, akg = t & 3;
    int gmA = row0 + am;
    int kkB = t >> 4, ngB = t & 15;

    float4 ra = make_float4(0.f,0.f,0.f,0.f), rb;
    if (gmA < M) ra = *(const float4*)&A[(size_t)gmA * 512 + akg * 4];
    rb = *(const float4*)&B[(size_t)kkB * ldb + col0 + ngB * 4];

    for (int it = 0; it < 32; it++) {
        As[akg*4+0][am] = ra.x; As[akg*4+1][am] = ra.y;
        As[akg*4+2][am] = ra.z; As[akg*4+3][am] = ra.w;
        Bs[kkB][ngB*4+0] = rb.x; Bs[kkB][ngB*4+1] = rb.y;
        Bs[kkB][ngB*4+2] = rb.z; Bs[kkB][ngB*4+3] = rb.w;
        __syncthreads();
        if (it < 31) {
            int k0 = (it + 1) * 16;
            ra = (gmA < M) ? *(const float4*)&A[(size_t)gmA*512 + k0 + akg*4]
                           : make_float4(0.f,0.f,0.f,0.f);
            rb = *(const float4*)&B[(size_t)(k0 + kkB) * ldb + col0 + ngB * 4];
        }
#pragma unroll
        for (int kk = 0; kk < 16; kk++) {
            ull b0 = *(const ull*)&Bs[kk][tx*4];
            ull b1 = *(const ull*)&Bs[kk][tx*4+2];
            float4 a = *(const float4*)&As[kk][ty*4];
            ull a0=pack2(a.x,a.x), a1=pack2(a.y,a.y);
            ull a2=pack2(a.z,a.z), a3=pack2(a.w,a.w);
            FMA2(acc[0][0],a0,b0); FMA2(acc[0][1],a0,b1);
            FMA2(acc[1][0],a1,b0); FMA2(acc[1][1],a1,b1);
            FMA2(acc[2][0],a2,b0); FMA2(acc[2][1],a2,b1);
            FMA2(acc[3][0],a3,b0); FMA2(acc[3][1],a3,b1);
        }
        __syncthreads();
    }
#pragma unroll
    for (int i = 0; i < 4; i++) {
        int gm = row0 + ty * 4 + i;
        if (gm >= M) continue;
#pragma unroll
        for (int j = 0; j < 2; j++) {
            float lo, hi;
            unpack2(acc[i][j], lo, hi);
            int c = col0 + tx * 4 + j * 2;
            if (c < N)     out[(size_t)gm * N + c]     = lo;
            if (c + 1 < N) out[(size_t)gm * N + c + 1] = hi;
        }
    }
}

// ================= Per-round fused GEMM from A=g_pair (M=128, K=512):
//  xt<16 : scores = (pair@KW^T)*NSCALE + cs      (N=1000, ld=1001)
//  xt<24 : q      =  pair@Wq^T + bq              (N=512)
//  xt<32 : kpair  =  pair@Wk^T + bk              (N=512)
//  xt<56 : giP    =  pair@W_ih^T + b_ih          (N=1536)
__global__ __launch_bounds__(256) void k_biggemm(
    const float* __restrict__ Wq, const float* __restrict__ bq,
    const float* __restrict__ Wk, const float* __restrict__ bk,
    const float* __restrict__ W_ih, const float* __restrict__ b_ih)
{
    __shared__ __align__(16) float As[16][36];
    __shared__ __align__(16) float Bs[16][68];
    int xt = blockIdx.x;
    const float *Wp, *bp; float *op; int N, ld; float scale; int col0;
    if (xt < 16)      { Wp = g_KW; bp = g_cs; op = g_scores; N = RR;  ld = RR+1; scale = NSCALE; col0 = xt * 64; }
    else if (xt < 24) { Wp = Wq;   bp = bq;   op = g_q;      N = EE;  ld = EE;   scale = 1.f;    col0 = (xt-16) * 64; }
    else if (xt < 32) { Wp = Wk;   bp = bk;   op = g_kpair;  N = EE;  ld = EE;   scale = 1.f;    col0 = (xt-24) * 64; }
    else              { Wp = W_ih; bp = b_ih; op = g_giP;    N = G3;  ld = G3;   scale = 1.f;    col0 = (xt-32) * 64; }
    int row0 = blockIdx.y * 32;
    int t = threadIdx.x, tx = t & 15, ty = t >> 4;
    ull acc[2][2] = {{0ULL,0ULL},{0ULL,0ULL}};

    int am = t >> 2, akg = t & 3;
    bool hasA = (t < 128);
    int gmA = row0 + am;
    int bn = t >> 2, bkg = t & 3;
    int gnB = col0 + bn;

    float4 ra = make_float4(0.f,0.f,0.f,0.f), rb = make_float4(0.f,0.f,0.f,0.f);
    if (hasA) ra = *(const float4*)&g_pair[(size_t)gmA * 512 + akg * 4];
    if (gnB < N) rb = *(const float4*)&Wp[(size_t)gnB * 512 + bkg * 4];

    for (int it = 0; it < 32; it++) {
        if (hasA) {
            As[akg*4+0][am] = ra.x; As[akg*4+1][am] = ra.y;
            As[akg*4+2][am] = ra.z; As[akg*4+3][am] = ra.w;
        }
        Bs[bkg*4+0][bn] = rb.x; Bs[bkg*4+1][bn] = rb.y;
        Bs[bkg*4+2][bn] = rb.z; Bs[bkg*4+3][bn] = rb.w;
        __syncthreads();
        if (it < 31) {
            int k0 = (it + 1) * 16;
            if (hasA) ra = *(const float4*)&g_pair[(size_t)gmA*512 + k0 + akg*4];
            rb = (gnB < N) ? *(const float4*)&Wp[(size_t)gnB*512 + k0 + bkg*4]
                           : make_float4(0.f,0.f,0.f,0.f);
        }
#pragma unroll
        for (int kk = 0; kk < 16; kk++) {
            ull b0 = *(const ull*)&Bs[kk][tx*4];
            ull b1 = *(const ull*)&Bs[kk][tx*4+2];
            float2 a = *(const float2*)&As[kk][ty*2];
            ull a0=pack2(a.x,a.x), a1=pack2(a.y,a.y);
            FMA2(acc[0][0],a0,b0); FMA2(acc[0][1],a0,b1);
            FMA2(acc[1][0],a1,b0); FMA2(acc[1][1],a1,b1);
        }
        __syncthreads();
    }
#pragma unroll
    for (int i = 0; i < 2; i++) {
        int gm = row0 + ty * 2 + i;
        float* orow = op + (size_t)gm * ld;
#pragma unroll
        for (int j = 0; j < 2; j++) {
            float lo, hi;
            unpack2(acc[i][j], lo, hi);
            int c = col0 + tx * 4 + j * 2;
            if (c < N)     orow[c]     = lo * scale + bp[c];
            if (c + 1 < N) orow[c + 1] = hi * scale + bp[c + 1];
        }
    }
}

// ================= giMix: gi = prob[:1000] @ GI_emb + p_pair * giP
// A = g_prob (ld 1001, scalar guarded loads), B = GI_emb (K-row-major, ld G3).
// Output row m -> g_gi[(m*16 + dslot[m]) * G3]. M=128, N=1536, TM=32.
__global__ __launch_bounds__(256) void k_giMix() {
    __shared__ __align__(16) float As[16][36];
    __shared__ __align__(16) float Bs[16][68];
    int col0 = blockIdx.x * 64, row0 = blockIdx.y * 32;
    int t = threadIdx.x, tx = t & 15, ty = t >> 4;
    ull acc[2][2] = {{0ULL,0ULL},{0ULL,0ULL}};

    int am = t >> 2, akg = t & 3;
    bool hasA = (t < 128);
    int gmA = row0 + am;
    int kkB = t >> 4, ngB = t & 15;

    float pa[4];
    float4 rb;
    if (hasA) {
        const float* pr = &g_prob[(size_t)gmA * (RR + 1)];
#pragma unroll
        for (int u = 0; u < 4; u++) { int k = akg * 4 + u; pa[u] = (k < RR) ? pr[k] : 0.f; }
    }
    rb = (kkB < RR) ? *(const float4*)&GI_emb[(size_t)kkB * G3 + col0 + ngB * 4]
                    : make_float4(0.f,0.f,0.f,0.f);

    const int NIT = 63;  // 63*16 = 1008 >= 1000
    for (int it = 0; it < NIT; it++) {
        if (hasA) {
            As[akg*4+0][am] = pa[0]; As[akg*4+1][am] = pa[1];
            As[akg*4+2][am] = pa[2]; As[akg*4+3][am] = pa[3];
        }
        Bs[kkB][ngB*4+0] = rb.x; Bs[kkB][ngB*4+1] = rb.y;
        Bs[kkB][ngB*4+2] = rb.z; Bs[kkB][ngB*4+3] = rb.w;
        __syncthreads();
        if (it < NIT - 1) {
            int k0 = (it + 1) * 16;
            if (hasA) {
                const float* pr = &g_prob[(size_t)gmA * (RR + 1)];
#pragma unroll
                for (int u = 0; u < 4; u++) { int k = k0 + akg * 4 + u; pa[u] = (k < RR) ? pr[k] : 0.f; }
            }
            int kb = k0 + kkB;
            rb = (kb < RR) ? *(const float4*)&GI_emb[(size_t)kb * G3 + col0 + ngB * 4]
                           : make_float4(0.f,0.f,0.f,0.f);
        }
#pragma unroll
        for (int kk = 0; kk < 16; kk++) {
            ull b0 = *(const ull*)&Bs[kk][tx*4];
            ull b1 = *(const ull*)&Bs[kk][tx*4+2];
            float2 a = *(const float2*)&As[kk][ty*2];
            ull a0=pack2(a.x,a.x), a1=pack2(a.y,a.y);
            FMA2(acc[0][0],a0,b0); FMA2(acc[0][1],a0,b1);
            FMA2(acc[1][0],a1,b0); FMA2(acc[1][1],a1,b1);
        }
        __syncthreads();
    }
#pragma unroll
    for (int i = 0; i < 2; i++) {
        int gm = row0 + ty * 2 + i;
        float pp = g_prob[(size_t)gm * (RR + 1) + RR];
        int slot = g_dslot[gm];
        float* orow = &g_gi[((size_t)gm * SS + slot) * G3];
        const float* gp = &g_giP[(size_t)gm * G3];
#pragma unroll
        for (int j = 0; j < 2; j++) {
            float lo, hi;
            unpack2(acc[i][j], lo, hi);
            int c = col0 + tx * 4 + j * 2;
            orow[c]     = lo + pp * gp[c];
            orow[c + 1] = hi + pp * gp[c + 1];
        }
    }
}

__global__ void k_h1emb(const float* __restrict__ b_hh) {
    int tk = blockIdx.x;
    const float* gi = &GI_emb[(size_t)tk * G3];
    for (int e = threadIdx.x; e < EE; e += blockDim.x) {
        float r = sigmf(gi[e] + b_hh[e]);
        float z = sigmf(gi[EE + e] + b_hh[EE + e]);
        float n = tanhf(gi[2 * EE + e] + r * b_hh[2 * EE + e]);
        H1_emb[(size_t)tk * EE + e] = (1.f - z) * n;
    }
}

__global__ void k_h1inc(const float* __restrict__ b_hh) {
    int b = blockIdx.x;
    int d = g_dslot[b];
    const float* gi = &g_gi[((size_t)b * SS + d) * G3];
    for (int e = threadIdx.x; e < EE; e += blockDim.x) {
        float r = sigmf(gi[e] + b_hh[e]);
        float z = sigmf(gi[EE + e] + b_hh[EE + e]);
        float n = tanhf(gi[2 * EE + e] + r * b_hh[2 * EE + e]);
        float h = (1.f - z) * n;
        g_h1[((size_t)b * SS + d) * EE + e] = h;
        g_newh1[(size_t)b * EE + e] = h;
    }
}

__global__ void k_cinit(const float* __restrict__ bq) {
    int r = blockIdx.x * 8 + (threadIdx.x >> 5);
    int lane = threadIdx.x & 31;
    if (r >= RR) return;
    float s = 0.f;
    for (int e = lane; e < EE; e += 32) s += bq[e] * g_Krel[(size_t)r * EE + e];
#pragma unroll
    for (int off = 16; off > 0; off >>= 1) s += __shfl_down_sync(0xffffffffu, s, off);
    if (lane == 0) g_cs[r] = NSCALE * s;
}

__device__ __forceinline__ float pair_elem(const float* gi, const float* gh,
                                           const float* h1, int e) {
    float r = sigmf(gi[e] + gh[e]);
    float z = sigmf(gi[EE + e] + gh[EE + e]);
    float n = tanhf(gi[2 * EE + e] + r * gh[2 * EE + e]);
    return (1.f - z) * n + z * h1[e];
}

__global__ void k_pairsel(const float* __restrict__ wfc, const float* __restrict__ bfc,
                          int npairs, int zloss, float* __restrict__ loss_out, int first) {
    int b = blockIdx.x, t = threadIdx.x;
    int w = t >> 5, lane = t & 31;
    __shared__ int sord[SS];
    __shared__ float sps[SS];
    __shared__ int sbestj;
    if (t < SS) {
        sord[t] = g_ord[b * SS + t];
        sps[t]  = g_pscore[b * SS + t];
    }
    int prev_sel = g_sel[b];
    __syncthreads();

    int j0 = -1, j1 = -1;
    if (first) {
        j0 = w;
        j1 = w + 8;
        if (j0 >= npairs) j0 = -1;
        if (j1 >= npairs) j1 = -1;
    } else {
        int cnt = 0, jj[2];
        if (prev_sel - 1 >= 0 && prev_sel - 1 < npairs) jj[cnt++] = prev_sel - 1;
        if (prev_sel >= 0 && prev_sel < npairs)         jj[cnt++] = prev_sel;
        if (w < cnt) j0 = jj[w];
    }
#pragma unroll
    for (int rep = 0; rep < 2; rep++) {
        int j = (rep == 0) ? j0 : j1;
        if (j >= 0) {
            const float* gi = p_gi(b, sord[j + 1]);
            const float* gh = p_ghh(b, sord[j]);
            const float* h1 = p_h1(b, sord[j]);
            float s = 0.f;
            for (int e = lane; e < EE; e += 32)
                s += pair_elem(gi, gh, h1, e) * wfc[e];
#pragma unroll
            for (int off = 16; off > 0; off >>= 1)
                s += __shfl_down_sync(0xffffffffu, s, off);
            if (lane == 0) {
                float sc = sigmf(s + bfc[0]);
                sps[j] = sc;
                g_pscore[b * SS + j] = sc;
            }
        }
    }
    __syncthreads();

    if (t == 0) {
        int bj = 0; float bs = sps[0];
        for (int j = 1; j < npairs; j++)
            if (sps[j] > bs) { bs = sps[j]; bj = j; }
        sbestj = bj;
        g_sel[b] = bj;
        if (zloss >= 0) loss_out[b * SS + zloss] = 0.f;
    }
    __syncthreads();
    int j = sbestj;
    const float* gi = p_gi(b, sord[j + 1]);
    const float* gh = p_ghh(b, sord[j]);
    const float* h1 = p_h1(b, sord[j]);
    for (int e = t; e < EE; e += 256)
        g_pair[(size_t)b * EE + e] = pair_elem(gi, gh, h1, e);
}

__device__ __forceinline__ float bsum(float v, float* red, int t) {
    red[t] = v; __syncthreads();
    for (int s = 128; s > 0; s >>= 1) { if (t < s) red[t] += red[t + s]; __syncthreads(); }
    return red[0];
}
__device__ __forceinline__ float bmax(float v, float* red, int t) {
    red[t] = v; __syncthreads();
    for (int s = 128; s > 0; s >>= 1) { if (t < s) red[t] = fmaxf(red[t], red[t + s]); __syncthreads(); }
    return red[0];
}

__global__ void k_softmax(int lossidx, int L, int do_book,
                          float* __restrict__ loss_out, float* __restrict__ scores_out) {
    int b = blockIdx.x, t = threadIdx.x;
    __shared__ float red[256];
    const float* q  = &g_q[(size_t)b * EE];
    const float* kp = &g_kpair[(size_t)b * EE];
    const float* sc = &g_scores[(size_t)b * (RR + 1)];

    float part = 0.f;
    for (int e = t; e < EE; e += 256) part += q[e] * kp[e];
    float c1000 = bsum(part, red, t) * NSCALE;
    __syncthreads();

    float m = -3.4e38f;
    for (int k = t; k <= RR; k += 256)
        m = fmaxf(m, (k < RR) ? sc[k] : c1000);
    m = bmax(m, red, t);
    __syncthreads();

    float se = 0.f, sv = 0.f;
    for (int k = t; k <= RR; k += 256) {
        float v = ((k < RR) ? sc[k] : c1000) - m;
        float ev = expf(v);
        se += ev; sv += ev * v;
    }
    float Z = bsum(se, red, t);
    __syncthreads();
    float S2 = bsum(sv, red, t);
    if (t == 0) loss_out[b * SS + lossidx] = logf(Z) - S2 / Z;

    float* pr = &g_prob[(size_t)b * (RR + 1)];
    for (int k = t; k <= RR; k += 256) {
        float raw = (k < RR) ? sc[k] : c1000;
        pr[k] = expf(raw - m) / Z;
        if (scores_out) scores_out[(size_t)b * (RR + 1) + k] = raw;
    }
    if (t == 0 && do_book) {
        int sel = g_sel[b];
        int* ord = &g_ord[b * SS];
        float* ps = &g_pscore[b * SS];
        int slot = ord[sel];
        g_dslot[b] = slot;
        g_src[b * SS + slot] = -1;
        for (int i = sel + 1; i < L - 1; i++) { ord[i] = ord[i + 1]; ps[i] = ps[i + 1]; }
    }
}

// ---------------- host ----------------
extern "C" void kernel_launch(void* const* d_in, const int* in_sizes, int n_in,
                              void* d_out, int out_size) {
    const int*   tokens = (const int*)  d_in[0];
    const float* emb    = (const float*)d_in[1];
    const float* W_ih   = (const float*)d_in[2];
    const float* W_hh   = (const float*)d_in[3];
    const float* b_ih   = (const float*)d_in[4];
    const float* b_hh   = (const float*)d_in[5];
    const float* w_fc   = (const float*)d_in[6];
    const float* b_fc   = (const float*)d_in[7];
    const float* Wq     = (const float*)d_in[8];
    const float* bq     = (const float*)d_in[9];
    const float* Wk     = (const float*)d_in[10];
    const float* bk     = (const float*)d_in[11];

    float* out_scores = (float*)d_out;                         // 128 x 1001
    float* out_loss   = (float*)d_out + (size_t)BB * (RR + 1); // 128 x 16

    float *GI, *H1, *GHH, *Krel, *KW, *newh1, *ghh;
    cudaGetSymbolAddress((void**)&GI, GI_emb);
    cudaGetSymbolAddress((void**)&H1, H1_emb);
    cudaGetSymbolAddress((void**)&GHH, GHH_emb);
    cudaGetSymbolAddress((void**)&Krel, g_Krel);
    cudaGetSymbolAddress((void**)&KW, g_KW);
    cudaGetSymbolAddress((void**)&newh1, g_newh1);
    cudaGetSymbolAddress((void**)&ghh, g_ghh);

    // ---- init (once per call) ----
    k_init<<<BB, 32>>>(tokens);
    gemm_t<64><<<dim3(24, 16), 256>>>(emb, W_ih, b_ih, GI, RR, G3, G3, 0, 1.f);
    k_h1emb<<<RR, 256>>>(b_hh);
    gemm_t<64><<<dim3(24, 16), 256>>>(H1, W_hh, b_hh, GHH, RR, G3, G3, 0, 1.f);
    gemm_t<64><<<dim3(8, 16), 256>>>(emb, Wk, bk, Krel, RR, EE, EE, 0, 1.f);
    k_gemm_kn<<<dim3(8, 16), 256>>>(Krel, Wq, KW, RR, EE, EE);
    k_cinit<<<125, 256>>>(bq);

    // ---- 14 merge rounds ----
    for (int i = 0; i < 14; i++) {
        int L = SS - i;
        k_pairsel<<<BB, 256>>>(w_fc, b_fc, L - 1, -1, out_loss, i == 0);
        k_biggemm<<<dim3(56, 4), 256>>>(Wq, bq, Wk, bk, W_ih, b_ih);
        k_softmax<<<BB, 256>>>(i, L, 1, out_loss, NULL);
        k_giMix<<<dim3(24, 4), 256>>>();
        k_h1inc<<<BB, 256>>>(b_hh);
        gemm_t<32><<<dim3(24, 4), 256>>>(newh1, W_hh, b_hh, ghh, BB, G3, G3, 1, 1.f);
    }
    // ---- final round (L=2) + output attention ----
    k_pairsel<<<BB, 256>>>(w_fc, b_fc, 1, 14, out_loss, 0);
    k_biggemm<<<dim3(32, 4), 256>>>(Wq, bq, Wk, bk, W_ih, b_ih);
    k_softmax<<<BB, 256>>>(15, 0, 0, out_loss, out_scores);
}